// round 8
// baseline (speedup 1.0000x reference)
#include <cuda_runtime.h>
#include <cuda_bf16.h>

// Problem constants (fixed shapes from reference)
#define NB     64
#define CC     256
#define EMB    16
#define HW     3136                 // 56*56
#define IDX    16                   // ceil(256^(0.5))
#define SCALEF (256.0f / 240.0f)    // c / (c - INDEX)

#define TOTAL4   ((unsigned)NB * CC * HW / 4)  // 12,845,056 float4
#define SLAB4    (HW / 4)                      // 784 float4 per (n,c) slab
#define BLK_F4   2048u                         // float4 per block (256 thr * 8)
#define BLKS_PER_N 98u                         // 2048*98 == 256*784 exactly
#define NBLOCKS  (TOTAL4 / BLK_F4)             // 6272 == 98*64

// ---------------------------------------------------------------------------
// Single fused kernel. Each block owns 2048 contiguous float4, which always
// lie inside ONE sample n (2048*98 == per-sample float4 count exactly).
//
// Prologue (per block, redundant across the 98 blocks of a sample but
// DRAM-free: table is 16 KB, L2-resident; issue slots are only ~8% busy):
//   activ[c] = embeds[n]·table[:,c], rank-count to find the sorted-index-16
//   value, build s_mult[c] in smem.
//
// Stream phase: batch-8 LDG.128.CS -> scale -> STG.128.CS. launch_bounds
// (256,4) gives a 64-reg budget so all 8 loads are genuinely in flight
// (the default 32-reg cap was limiting MLP to ~2).
// ---------------------------------------------------------------------------
__global__ void __launch_bounds__(256, 4)
drop_fused_kernel(const float4* __restrict__ x,
                  const float*  __restrict__ embeds,
                  const float*  __restrict__ table,
                  float4* __restrict__ out) {
    __shared__ float s_emb[EMB];
    __shared__ float s_act[CC];
    __shared__ float s_mult[CC];
    __shared__ float s_thr;

    const unsigned t = threadIdx.x;
    const unsigned n = blockIdx.x / BLKS_PER_N;

    // --- prologue: per-sample channel mask -------------------------------
    if (t < EMB) s_emb[t] = embeds[n * EMB + t];
    __syncthreads();

    float a = 0.0f;
#pragma unroll
    for (int e = 0; e < EMB; e++)
        a = fmaf(s_emb[e], table[e * CC + t], a);   // coalesced across t
    s_act[t] = a;
    __syncthreads();

    // Rank of this thread's value among the 256 row values (float4 reads).
    const float4* act4 = (const float4*)s_act;
    int less = 0, leq = 0;
#pragma unroll 8
    for (int j = 0; j < CC / 4; j++) {
        const float4 w = act4[j];
        less += (w.x <  a) + (w.y <  a) + (w.z <  a) + (w.w <  a);
        leq  += (w.x <= a) + (w.y <= a) + (w.z <= a) + (w.w <= a);
    }
    // Sorted-index-IDX element: #{< v} <= IDX and #{<= v} > IDX (tie-safe).
    if (less <= IDX && leq > IDX) s_thr = a;
    __syncthreads();

    s_mult[t] = (s_thr <= s_act[t]) ? SCALEF : 0.0f;
    __syncthreads();

    // --- stream phase: 8 float4 per thread, batched loads ----------------
    const unsigned base = blockIdx.x * BLK_F4 + t;

    float  m[8];
    float4 v[8];
#pragma unroll
    for (int k = 0; k < 8; k++) {
        const unsigned i = base + (unsigned)k * 256u;
        m[k] = s_mult[(i / SLAB4) & (CC - 1)];       // channel within sample
    }
#pragma unroll
    for (int k = 0; k < 8; k++)
        v[k] = __ldcs(&x[base + (unsigned)k * 256u]);
#pragma unroll
    for (int k = 0; k < 8; k++) {
        v[k].x *= m[k]; v[k].y *= m[k]; v[k].z *= m[k]; v[k].w *= m[k];
        __stcs(&out[base + (unsigned)k * 256u], v[k]);
    }
}

extern "C" void kernel_launch(void* const* d_in, const int* in_sizes, int n_in,
                              void* d_out, int out_size) {
    const float* x      = (const float*)d_in[0];   // [64,256,56,56]
    const float* embeds = (const float*)d_in[1];   // [64,16]
    const float* table  = (const float*)d_in[2];   // [16,256]
    float* out = (float*)d_out;

    drop_fused_kernel<<<NBLOCKS, 256>>>((const float4*)x, embeds, table,
                                        (float4*)out);
}

// round 9
// speedup vs baseline: 1.3681x; 1.3681x over previous
#include <cuda_runtime.h>
#include <cuda_bf16.h>

// Problem constants (fixed shapes from reference)
#define NB     64
#define CC     256
#define EMB    16
#define HW     3136                 // 56*56
#define IDX    16                   // ceil(256^(0.5))
#define SCALEF (256.0f / 240.0f)    // c / (c - INDEX)

#define TOTAL4  ((unsigned)NB * CC * HW / 4)   // 12,845,056 float4
#define SLAB4   (HW / 4)                       // 784 float4 per (n,c) slab
#define BLK_F4  2048u                          // float4 per block (256 thr * 8)
#define NBLOCKS (TOTAL4 / BLK_F4)              // 6272

// Per-(n,c) multiplier: SCALEF if channel kept, 0 if dropped. 16 KB.
__device__ float g_mult[NB * CC];

// ---------------------------------------------------------------------------
// Kernel 1: one block per sample n (64 blocks). activ = embeds[n]·table,
// rank-count for the sorted-index-16 value, emit per-channel multiplier.
// Tiny (~2 us); runs once, NOT fused (R7 showed the 98x-redundant fused
// prologue saturates the issue/ALU ports and starves the stream).
// ---------------------------------------------------------------------------
__global__ void drop_thresh_kernel(const float* __restrict__ embeds,
                                   const float* __restrict__ table) {
    __shared__ float s_emb[EMB];
    __shared__ float s_act[CC];
    __shared__ float s_thr;

    const int n = blockIdx.x;
    const int c = threadIdx.x;

    if (c < EMB) s_emb[c] = embeds[n * EMB + c];
    __syncthreads();

    float a = 0.0f;
#pragma unroll
    for (int e = 0; e < EMB; e++)
        a = fmaf(s_emb[e], table[e * CC + c], a);   // coalesced across c
    s_act[c] = a;
    __syncthreads();

    // Rank of this thread's value among the 256 row values (float4 reads).
    const float4* act4 = (const float4*)s_act;
    int less = 0, leq = 0;
#pragma unroll 8
    for (int j = 0; j < CC / 4; j++) {
        const float4 w = act4[j];
        less += (w.x <  a) + (w.y <  a) + (w.z <  a) + (w.w <  a);
        leq  += (w.x <= a) + (w.y <= a) + (w.z <= a) + (w.w <= a);
    }
    // Sorted-index-IDX element: #{< v} <= IDX and #{<= v} > IDX (tie-safe).
    if (less <= IDX && leq > IDX) s_thr = a;
    __syncthreads();

    g_mult[n * CC + c] = (s_thr <= a) ? SCALEF : 0.0f;
}

// ---------------------------------------------------------------------------
// Kernel 2: pure HBM stream. Each block owns 2048 contiguous float4.
// __launch_bounds__(256, 4) raises the register budget to 64 so the batch-8
// loads are genuinely in flight (the default 32-reg cap limited MLP to ~2-3
// in R6: DRAM stuck at 73.7%). Branch-free: x finite => x*0 == 0 exactly.
// Touch-once data on both sides: cache-streaming loads/stores.
// ---------------------------------------------------------------------------
__global__ void __launch_bounds__(256, 4)
drop_apply_kernel(const float4* __restrict__ x, float4* __restrict__ out) {
    const unsigned base = blockIdx.x * BLK_F4 + threadIdx.x;

    float m[8];
#pragma unroll
    for (int k = 0; k < 8; k++)
        m[k] = g_mult[(base + (unsigned)k * 256u) / SLAB4];  // L1/L2-resident

    float4 v[8];
#pragma unroll
    for (int k = 0; k < 8; k++)
        v[k] = __ldcs(&x[base + (unsigned)k * 256u]);        // 8 LDG.128.CS batched

#pragma unroll
    for (int k = 0; k < 8; k++) {
        v[k].x *= m[k]; v[k].y *= m[k]; v[k].z *= m[k]; v[k].w *= m[k];
        __stcs(&out[base + (unsigned)k * 256u], v[k]);
    }
}

extern "C" void kernel_launch(void* const* d_in, const int* in_sizes, int n_in,
                              void* d_out, int out_size) {
    const float* x      = (const float*)d_in[0];   // [64,256,56,56]
    const float* embeds = (const float*)d_in[1];   // [64,16]
    const float* table  = (const float*)d_in[2];   // [16,256]
    float* out = (float*)d_out;

    drop_thresh_kernel<<<NB, CC>>>(embeds, table);
    drop_apply_kernel<<<NBLOCKS, 256>>>((const float4*)x, (float4*)out);
}